// round 15
// baseline (speedup 1.0000x reference)
#include <cuda_runtime.h>
#include <cuda_bf16.h>
#include <cstdint>

// Problem constants
#define NN 32
#define CC 512
#define CM 128
#define HH 48
#define WW 48
#define HWP 2304
#define PP 512
#define KR 9
#define NHALF (NN/2)

// ---------------- scratch (device globals; no allocation allowed) ----------
__device__ float g_pool[NN*CC*12];   // [n][c][12]: mean, 9 region-maxes, pad
__device__ float g_gk1[NN*CM];
__device__ float g_sk[NN*CM*KR];
// bf16-triple A-layout buffers (u32 words; 6 words per 4 fp32 k-elements)
__device__ __align__(16) uint32_t g_dynWT[(size_t)NN*KR*CM*192]; // [n][kk][o][192]
__device__ __align__(16) uint32_t g_WcT[CM*768];                 // [o][768]
__device__ __align__(16) uint32_t g_WfT[PP*192];                 // [p][192]
__device__ __align__(16) float g_f[(size_t)NN*CM*HWP];           // [n][o][hw]
__device__ __align__(16) float g_y[(size_t)NN*CM*HWP];           // [n][o][hw]

// ---------------- helpers ----------------------------------------------------
__device__ __forceinline__ uint32_t su32(const void* p){
    uint32_t a; asm("{ .reg .u64 t; cvta.to.shared.u64 t, %1; cvt.u32.u64 %0, t; }"
                    : "=r"(a) : "l"(p)); return a;
}
__device__ __forceinline__ void cpa16(uint32_t d, const void* s){
    asm volatile("cp.async.cg.shared.global [%0], [%1], 16;" :: "r"(d), "l"(s));
}
__device__ __forceinline__ void cpcommit(){ asm volatile("cp.async.commit_group;" ::: "memory"); }
template<int N> __device__ __forceinline__ void cpwait(){
    asm volatile("cp.async.wait_group %0;" :: "n"(N) : "memory");
}
// bf16 m16n8k16 MMA
__device__ __forceinline__ void mma16(float* c, const uint32_t* a, const uint32_t* b){
    asm volatile("mma.sync.aligned.m16n8k16.row.col.f32.bf16.bf16.f32 "
        "{%0,%1,%2,%3}, {%4,%5,%6,%7}, {%8,%9}, {%0,%1,%2,%3};"
        : "+f"(c[0]), "+f"(c[1]), "+f"(c[2]), "+f"(c[3])
        : "r"(a[0]), "r"(a[1]), "r"(a[2]), "r"(a[3]), "r"(b[0]), "r"(b[1]));
}
// ldmatrix x4 (b16, non-transposed)
__device__ __forceinline__ void ldmA(uint32_t* a, uint32_t saddr){
    asm volatile("ldmatrix.sync.aligned.m8n8.x4.shared.b16 {%0,%1,%2,%3}, [%4];"
      : "=r"(a[0]), "=r"(a[1]), "=r"(a[2]), "=r"(a[3]) : "r"(saddr));
}
// 2-term bf16 split: f = hi + lo (+ O(2^-17 f))
__device__ __forceinline__ void bsplit(float f, uint16_t& h, uint16_t& l){
    __nv_bfloat16 bh = __float2bfloat16(f);
    float r = f - __bfloat162float(bh);
    __nv_bfloat16 bl = __float2bfloat16(r);
    h = __bfloat16_as_ushort(bh);
    l = __bfloat16_as_ushort(bl);
}
__device__ __forceinline__ uint32_t pk(uint16_t a, uint16_t b){
    return (uint32_t)a | ((uint32_t)b << 16);
}
// A triple encode: 4 consecutive fp32 k -> 6 u32 words
__device__ __forceinline__ void storeA4(uint32_t* dst, float4 v){
    uint16_t h0,l0,h1,l1,h2,l2,h3,l3;
    bsplit(v.x, h0, l0); bsplit(v.y, h1, l1);
    bsplit(v.z, h2, l2); bsplit(v.w, h3, l3);
    *(uint2*)(dst)     = make_uint2(pk(h0,l0), pk(h0,h1));
    *(uint2*)(dst + 2) = make_uint2(pk(l1,h1), pk(h2,l2));
    *(uint2*)(dst + 4) = make_uint2(pk(h2,h3), pk(l3,h3));
}
// B triple encode: two consecutive fp32 k rows (k even), 4 cols -> 3 swizzled uint4
__device__ __forceinline__ void storeB2x4(uint32_t* bw, int wp, int bn4,
                                          const float* r0, const float* r1){
    uint32_t w0[4], w1[4], w2[4];
#pragma unroll
    for (int j = 0; j < 4; j++) {
        uint16_t H0,L0,H1,L1;
        bsplit(r0[j], H0, L0);
        bsplit(r1[j], H1, L1);
        w0[j] = pk(H0,H0); w1[j] = pk(L0,H1); w2[j] = pk(H1,L1);
    }
    *(uint4*)(bw + (wp  )*128 + (bn4 ^ (((wp  )&3)<<3))) = make_uint4(w0[0],w0[1],w0[2],w0[3]);
    *(uint4*)(bw + (wp+1)*128 + (bn4 ^ (((wp+1)&3)<<3))) = make_uint4(w1[0],w1[1],w1[2],w1[3]);
    *(uint4*)(bw + (wp+2)*128 + (bn4 ^ (((wp+2)&3)<<3))) = make_uint4(w2[0],w2[1],w2[2],w2[3]);
}

// smem geometry (u32 units). A: [128 rows][48 words + pad->52]; B: [48 words][128 cols]
#define AP 52
#define AWBUF (128*AP)          // 6656
#define BWBUF (48*128)          // 6144
#define BUFW  (AWBUF + BWBUF)   // 12800
#define SMEM_BYTES (2*BUFW*4)   // 102400

// conv halo-B geometry: [48 words][200 cols] (4 rows x 50 w, padded edges).
// CPW = 200: fragment load bank = (8*lr + lq) mod 32 -> permutation, conflict-free.
#define CPW 200
#define CBWORDS (48*CPW)                       // 9600 u32
#define CONV_SMEM ((2*AWBUF + CBWORDS)*4)      // 91648 B

// ---------------- kernel 1: mean + 3x3 adaptive max pool (coalesced) -------
__global__ void pool_kernel(const float* __restrict__ x) {
    const int g = threadIdx.x >> 4, l = threadIdx.x & 15;
    const int c = blockIdx.x*16 + g, n = blockIdx.y;
    const float4* xp = (const float4*)(x + (size_t)(n*CC + c)*HWP);

    float s = 0.f;
    float mx[KR];
#pragma unroll
    for (int r = 0; r < KR; r++) {
        const int hb = r/3, wb = r - (r/3)*3;
        float mr = -3.402823466e38f;
#pragma unroll
        for (int j = 0; j < 4; j++) {
            int idx = j*16 + l;
            int row = idx >> 2, w4 = idx & 3;
            float4 v = xp[(hb*16 + row)*12 + wb*4 + w4];
            s += v.x + v.y + v.z + v.w;
            mr = fmaxf(mr, fmaxf(fmaxf(v.x, v.y), fmaxf(v.z, v.w)));
        }
        mx[r] = mr;
    }
#pragma unroll
    for (int o = 8; o > 0; o >>= 1) {
        s += __shfl_down_sync(0xffffffffu, s, o, 16);
#pragma unroll
        for (int r = 0; r < KR; r++)
            mx[r] = fmaxf(mx[r], __shfl_down_sync(0xffffffffu, mx[r], o, 16));
    }
    if (l == 0) {
        float* dst = g_pool + (size_t)(n*CC + c)*12;
        dst[0] = s * (1.0f/(float)HWP);
#pragma unroll
        for (int r = 0; r < KR; r++) dst[1+r] = mx[r];
        dst[10] = 0.f; dst[11] = 0.f;
    }
}

// ---------------- kernel 2: branches (full-chip parallel) -------------------
__global__ void __launch_bounds__(256) branch_kernel(
    const float* __restrict__ Wc, const float* __restrict__ bc) {
    const int og = blockIdx.x, n = blockIdx.y;
    const int lane = threadIdx.x & 31, w = threadIdx.x >> 5;
    const int o0 = og*16 + w*2;
    const int o1 = o0 + 1;

    const float* pb = g_pool + (size_t)n*CC*12;
    const float* wr0 = Wc + (size_t)o0*CC;
    const float* wr1 = Wc + (size_t)o1*CC;

    float a0[10], a1[10];
#pragma unroll
    for (int j = 0; j < 10; j++) { a0[j] = 0.f; a1[j] = 0.f; }

#pragma unroll
    for (int i = 0; i < 16; i++) {
        const int c = lane + i*32;
        const float wv0 = __ldg(&wr0[c]);
        const float wv1 = __ldg(&wr1[c]);
        const float4* pc = (const float4*)(pb + c*12);
        float4 p0 = __ldg(pc), p1 = __ldg(pc+1), p2 = __ldg(pc+2);
        a0[0] += wv0*p0.x; a0[1] += wv0*p0.y; a0[2] += wv0*p0.z; a0[3] += wv0*p0.w;
        a0[4] += wv0*p1.x; a0[5] += wv0*p1.y; a0[6] += wv0*p1.z; a0[7] += wv0*p1.w;
        a0[8] += wv0*p2.x; a0[9] += wv0*p2.y;
        a1[0] += wv1*p0.x; a1[1] += wv1*p0.y; a1[2] += wv1*p0.z; a1[3] += wv1*p0.w;
        a1[4] += wv1*p1.x; a1[5] += wv1*p1.y; a1[6] += wv1*p1.z; a1[7] += wv1*p1.w;
        a1[8] += wv1*p2.x; a1[9] += wv1*p2.y;
    }
#pragma unroll
    for (int off = 16; off > 0; off >>= 1)
#pragma unroll
        for (int j = 0; j < 10; j++) {
            a0[j] += __shfl_down_sync(0xffffffffu, a0[j], off);
            a1[j] += __shfl_down_sync(0xffffffffu, a1[j], off);
        }
    if (lane == 0) {
        const float bv0 = bc[o0], bv1 = bc[o1];
        g_gk1[n*CM + o0] = fmaxf(a0[0] + bv0, 0.f);
        g_gk1[n*CM + o1] = fmaxf(a1[0] + bv1, 0.f);
#pragma unroll
        for (int r = 0; r < KR; r++) {
            g_sk[(size_t)(n*CM + o0)*KR + r] = fmaxf(a0[1+r] + bv0, 0.f);
            g_sk[(size_t)(n*CM + o1)*KR + r] = fmaxf(a1[1+r] + bv1, 0.f);
        }
    }
}

// ---------------- weight triple-encode (one-shot, tiny) ---------------------
__global__ void wtrip_kernel(const float* __restrict__ W, uint32_t* __restrict__ T, int Kd) {
    const int idx = blockIdx.x*256 + threadIdx.x;
    const int gpr = Kd >> 2;
    const int row = idx / gpr, g = idx - row*gpr;
    float4 v = *(const float4*)(W + (size_t)row*Kd + 4*g);
    storeA4(T + (size_t)row*(gpr*6) + 6*g, v);
}

// ---------------- kernel 3: dynamic weights, emitted in trip layout ---------
__global__ void dynw_kernel(const float* __restrict__ Wkk, const float* __restrict__ bkk,
                            const float* __restrict__ Wck, const float* __restrict__ bck) {
    int r = blockIdx.x, n = blockIdx.y;
    int tid = threadIdx.x;
    __shared__ float s_gk[CM], s_sk[CM];
    if (tid < CM) {
        float gk1 = g_gk1[n*CM + tid];
        s_gk[tid] = gk1 * Wkk[r] + bkk[r];
        s_sk[tid] = g_sk[(size_t)(n*CM + tid)*KR + r];
    }
    __syncthreads();
    uint32_t* dst = g_dynWT + (size_t)(n*KR + r)*CM*192;
#pragma unroll
    for (int i = 0; i < 16; i++) {
        const int idx = tid + i*256;
        const int o = idx >> 5, gc = idx & 31;
        const int c4 = gc*4;
        const float wa = Wck[o*2], wb = Wck[o*2+1], bo = bck[o];
        float4 v;
        v.x = fmaxf(wa*s_gk[c4]   + wb*s_sk[c4]   + bo, 0.f);
        v.y = fmaxf(wa*s_gk[c4+1] + wb*s_sk[c4+1] + bo, 0.f);
        v.z = fmaxf(wa*s_gk[c4+2] + wb*s_sk[c4+2] + bo, 0.f);
        v.w = fmaxf(wa*s_gk[c4+3] + wb*s_sk[c4+3] + bo, 0.f);
        storeA4(dst + (size_t)o*192 + gc*6, v);
    }
}

// ---------------- shared bf16 mma compute (ldmatrix A + LDS B) --------------
__device__ __forceinline__ void mma_compute(
    uint32_t aAddr, const uint32_t* pb, float acc[2][8][4],
    int wn, int lane)
{
    const int lq = lane >> 2, lr = lane & 3;
#pragma unroll
    for (int s = 0; s < 6; s++) {
        uint32_t a[2][4];
        ldmA(a[0], aAddr + s*32);
        ldmA(a[1], aAddr + 16*AP*4 + s*32);
        const int w0 = s*8 + lr;
        const int xr = (w0 & 3) << 3;
        const int nb = wn*64 + lq;
#pragma unroll
        for (int nt = 0; nt < 8; nt++) {
            const int col = (nb + nt*8) ^ xr;
            uint32_t b[2];
            b[0] = pb[w0*128 + col];
            b[1] = pb[(w0+4)*128 + col];
            mma16(acc[0][nt], a[0], b);
            mma16(acc[1][nt], a[1], b);
        }
    }
}

// ---------------- bf16x3 mma GEMM: C[n] = act(At @ B[n] + bias) --------------
// nOff: batch offset (half-batch pipelining across streams)
template<bool RELU>
__global__ void __launch_bounds__(256, 2) gemm_mma(
    const uint32_t* __restrict__ At, const float* __restrict__ B,
    float* __restrict__ C, const float* __restrict__ bias,
    int Kd, size_t BstrN, size_t CstrN, int nOff)
{
    extern __shared__ uint32_t sm[];
    const uint32_t sBase = su32(sm);

    const int tid = threadIdx.x, lane = tid & 31, wid = tid >> 5;
    const int wm = wid & 3, wn = wid >> 2;
    const int n0 = blockIdx.x * 128;
    const int m0 = blockIdx.y * 128;
    const int nb = blockIdx.z + nOff;
    const int W3 = (Kd >> 2) * 6;
    const float* Bp = B + (size_t)nb*BstrN + n0;
    float*       Cp = C + (size_t)nb*CstrN;

    const int kb2 = (tid >> 5) * 2;
    const int bn4 = (tid & 31) * 4;

    const uint32_t aAddr0 = sBase + (uint32_t)((wm*32 + (lane & 15))*AP + (lane >> 4)*4)*4;

    float acc[2][8][4];
#pragma unroll
    for (int i = 0; i < 2; i++)
#pragma unroll
        for (int j = 0; j < 8; j++)
#pragma unroll
            for (int t = 0; t < 4; t++) acc[i][j][t] = 0.f;

    float4 rB[2][2];

    auto cpA = [&](int it){
        const int buf = it & 1;
#pragma unroll
        for (int j = 0; j < 6; j++) {
            const int ch = tid + j*256;
            const int row = ch / 12, w16 = ch - row*12;
            cpa16(sBase + (uint32_t)(buf*BUFW + row*AP + w16*4)*4,
                  At + (size_t)(m0 + row)*W3 + it*48 + w16*4);
        }
        cpcommit();
    };
    auto ldgB = [&](int it){
        const int k0 = it * 32;
#pragma unroll
        for (int q = 0; q < 2; q++) {
            const int k = k0 + kb2 + q*16;
            rB[q][0] = *(const float4*)(Bp + (size_t)k*HWP + bn4);
            rB[q][1] = *(const float4*)(Bp + (size_t)(k+1)*HWP + bn4);
        }
    };
    auto stsB = [&](int buf){
        uint32_t* bw = sm + buf*BUFW + AWBUF;
#pragma unroll
        for (int q = 0; q < 2; q++)
            storeB2x4(bw, ((tid>>5) + q*8)*3, bn4, (const float*)&rB[q][0], (const float*)&rB[q][1]);
    };

    const int nIter = Kd / 32;
    cpA(0); ldgB(0); stsB(0); cpwait<0>(); __syncthreads();
    for (int it = 0; it < nIter; ++it) {
        const int cur = it & 1;
        if (it + 1 < nIter) { cpA(it + 1); ldgB(it + 1); }
        mma_compute(aAddr0 + cur*BUFW*4, sm + cur*BUFW + AWBUF, acc, wn, lane);
        if (it + 1 < nIter) { stsB(cur ^ 1); cpwait<0>(); __syncthreads(); }
    }

    const int lq = lane >> 2, lr = lane & 3;
#pragma unroll
    for (int mt = 0; mt < 2; mt++) {
        const int r0 = m0 + wm*32 + mt*16 + lq;
        const float bv0 = __ldg(&bias[r0]);
        const float bv1 = __ldg(&bias[r0 + 8]);
#pragma unroll
        for (int nt = 0; nt < 8; nt++) {
            const int cb = n0 + wn*64 + nt*8 + 2*lr;
            float2 v0 = make_float2(acc[mt][nt][0] + bv0, acc[mt][nt][1] + bv0);
            float2 v1 = make_float2(acc[mt][nt][2] + bv1, acc[mt][nt][3] + bv1);
            if (RELU) {
                v0.x = fmaxf(v0.x, 0.f); v0.y = fmaxf(v0.y, 0.f);
                v1.x = fmaxf(v1.x, 0.f); v1.y = fmaxf(v1.y, 0.f);
            }
            *(float2*)(Cp + (size_t)r0*HWP + cb)       = v0;
            *(float2*)(Cp + (size_t)(r0 + 8)*HWP + cb) = v1;
        }
    }
}

// ---------------- conv: halo-tiled implicit GEMM (bf16x3 mma) ----------------
__global__ void __launch_bounds__(256, 2) conv_mma(const float* __restrict__ b_ad, int nOff)
{
    extern __shared__ uint32_t sm[];
    const uint32_t sBase = su32(sm);
    uint32_t* bw = sm + 2*AWBUF;

    const int tid = threadIdx.x, lane = tid & 31, wid = tid >> 5;
    const int wm = wid & 3, wn = wid >> 2;   // wm: 32-o rows; wn: 48-hw cols
    const int bx = blockIdx.x;               // 24 tiles of 2 rows
    const int h0 = bx*2;
    const int hw0 = bx*96;
    const int nb  = blockIdx.y + nOff;
    const float* fb = g_f + (size_t)nb*CM*HWP;
    const uint32_t* dwt = g_dynWT + (size_t)nb*KR*CM*192;

    const uint32_t aAddr0 = sBase + (uint32_t)((wm*32 + (lane & 15))*AP + (lane >> 4)*4)*4;

    // zero the 8 pad columns (w=-1, w=48 per input row) for all 48 k-words
    for (int i = tid; i < 48*8; i += 256) {
        const int row = i >> 3, e = i & 7;
        const int r = e >> 1, side = e & 1;
        bw[row*CPW + r*50 + (side ? 49 : 0)] = 0;
    }

    float acc[2][6][4];
#pragma unroll
    for (int i = 0; i < 2; i++)
#pragma unroll
        for (int j = 0; j < 6; j++)
#pragma unroll
            for (int t = 0; t < 4; t++) acc[i][j][t] = 0.f;

    auto cpA = [&](int it){                 // it = chunk*9 + kk
        const int buf = it & 1;
        const int kk = it % 9, c48 = (it/9)*48;
        const uint32_t* src = dwt + (size_t)kk*CM*192;
#pragma unroll
        for (int j = 0; j < 6; j++) {
            const int ch = tid + j*256;
            const int row = ch / 12, w16 = ch - row*12;
            cpa16(sBase + (uint32_t)(buf*AWBUF + row*AP + w16*4)*4,
                  src + (size_t)row*192 + c48 + w16*4);
        }
        cpcommit();
    };

    auto loadB = [&](int chunk){
        const int c0 = chunk*32;
#pragma unroll
        for (int j = 0; j < 12; j++) {
            const int slot = tid + j*256;        // 0..3071 = 16 pairs x 192 pos
            const int p = slot / 192, pos = slot - p*192;
            const int r = pos / 48, w = pos - r*48;
            const int hin = h0 - 1 + r;
            const bool ok = (hin >= 0) && (hin < HH);
            float v0 = 0.f, v1 = 0.f;
            if (ok) {
                const float* fp = fb + (size_t)(c0 + 2*p)*HWP + hin*WW + w;
                v0 = __ldg(fp);
                v1 = __ldg(fp + HWP);
            }
            uint16_t H0,L0,H1,L1;
            bsplit(v0, H0, L0); bsplit(v1, H1, L1);
            uint32_t* q = bw + (3*p)*CPW + r*50 + 1 + w;
            q[0]     = pk(H0,H0);
            q[CPW]   = pk(L0,H1);
            q[2*CPW] = pk(H1,L1);
        }
    };

    const int lq = lane >> 2, lr = lane & 3;
    const int colb = (wn + 1)*50 + 1 + lq;   // fragment col base (tap 0 center)

    auto mmaStep = [&](int buf, int tapoff){
        const uint32_t aAddr = aAddr0 + (uint32_t)(buf*AWBUF)*4;
#pragma unroll
        for (int s = 0; s < 6; s++) {
            uint32_t a[2][4];
            ldmA(a[0], aAddr + s*32);
            ldmA(a[1], aAddr + 16*AP*4 + s*32);
            const uint32_t* pb0 = bw + (s*8 + lr)*CPW + tapoff;
#pragma unroll
            for (int nt = 0; nt < 6; nt++) {
                const int col = colb + nt*8;
                uint32_t b[2];
                b[0] = pb0[col];
                b[1] = pb0[4*CPW + col];
                mma16(acc[0][nt], a[0], b);
                mma16(acc[1][nt], a[1], b);
            }
        }
    };

    cpA(0); cpwait<0>();
    for (int chunk = 0; chunk < 4; chunk++) {
        __syncthreads();                 // prior readers done / zeros+A visible
        loadB(chunk);
        __syncthreads();
#pragma unroll
        for (int kk = 0; kk < KR; kk++) {
            const int it = chunk*9 + kk;
            if (it + 1 < 36) cpA(it + 1);
            const int kh = kk/3 - 1, kw = kk - (kk/3)*3 - 1;
            mmaStep(it & 1, kh*50 + kw);
            if (it + 1 < 36) { cpwait<0>(); __syncthreads(); }
        }
    }

    // epilogue: y[o][hw0 + wn*48 + nt*8 + 2lr + {0,1}]
    float* yb = g_y + (size_t)nb*CM*HWP;
#pragma unroll
    for (int mt = 0; mt < 2; mt++) {
        const int o0 = wm*32 + mt*16 + lq;
        const float bv0 = __ldg(&b_ad[o0]);
        const float bv1 = __ldg(&b_ad[o0 + 8]);
#pragma unroll
        for (int nt = 0; nt < 6; nt++) {
            const int cb = hw0 + wn*48 + nt*8 + 2*lr;
            float2 v0 = make_float2(acc[mt][nt][0] + bv0, acc[mt][nt][1] + bv0);
            float2 v1 = make_float2(acc[mt][nt][2] + bv1, acc[mt][nt][3] + bv1);
            *(float2*)(yb + (size_t)o0*HWP + cb)       = v0;
            *(float2*)(yb + (size_t)(o0 + 8)*HWP + cb) = v1;
        }
    }
}

// ---------------- launch -----------------------------------------------------
// 2-stream schedule (round-12-proven resource footprint: 1 stream + events):
//   s2: pool -> branch -> dynw [evJoin] -> (wait evW) gemm1(h1) -> conv(h1) -> gemm2(h1) [evA]
//   0 : wtrips [evW] -> gemm1(h0) -> (wait evJoin) conv(h0) -> gemm2(h0) -> (wait evA)
extern "C" void kernel_launch(void* const* d_in, const int* in_sizes, int n_in,
                              void* d_out, int out_size) {
    const float* x    = (const float*)d_in[0];
    const float* Wc   = (const float*)d_in[1];
    const float* bc   = (const float*)d_in[2];
    const float* Wkk  = (const float*)d_in[3];
    const float* bkk  = (const float*)d_in[4];
    const float* Wck  = (const float*)d_in[5];
    const float* bck  = (const float*)d_in[6];
    const float* b_ad = (const float*)d_in[7];
    const float* Wf   = (const float*)d_in[8];
    const float* bf   = (const float*)d_in[9];
    float* out = (float*)d_out;

    float* df; float* dy;
    uint32_t* dWcT; uint32_t* dWfT;
    cudaGetSymbolAddress((void**)&df,   g_f);
    cudaGetSymbolAddress((void**)&dy,   g_y);
    cudaGetSymbolAddress((void**)&dWcT, g_WcT);
    cudaGetSymbolAddress((void**)&dWfT, g_WfT);

    cudaFuncSetAttribute(gemm_mma<true>,  cudaFuncAttributeMaxDynamicSharedMemorySize, SMEM_BYTES);
    cudaFuncSetAttribute(gemm_mma<false>, cudaFuncAttributeMaxDynamicSharedMemorySize, SMEM_BYTES);
    cudaFuncSetAttribute(conv_mma,        cudaFuncAttributeMaxDynamicSharedMemorySize, CONV_SMEM);

    cudaStream_t s2;
    cudaStreamCreateWithFlags(&s2, cudaStreamNonBlocking);
    cudaEvent_t evFork, evJoin, evW, evA;
    cudaEventCreateWithFlags(&evFork, cudaEventDisableTiming);
    cudaEventCreateWithFlags(&evJoin, cudaEventDisableTiming);
    cudaEventCreateWithFlags(&evW,    cudaEventDisableTiming);
    cudaEventCreateWithFlags(&evA,    cudaEventDisableTiming);

    // fork
    cudaEventRecord(evFork, 0);
    cudaStreamWaitEvent(s2, evFork, 0);

    // s2: side chain
    pool_kernel<<<dim3(CC/16, NN), 256, 0, s2>>>(x);
    branch_kernel<<<dim3(8, NN), 256, 0, s2>>>(Wc, bc);
    dynw_kernel<<<dim3(KR, NN), 256, 0, s2>>>(Wkk, bkk, Wck, bck);
    cudaEventRecord(evJoin, s2);

    // 0: weight encodes
    wtrip_kernel<<<CM*(CC/4)/256, 256>>>(Wc, dWcT, CC);
    wtrip_kernel<<<PP*(CM/4)/256, 256>>>(Wf, dWfT, CM);
    cudaEventRecord(evW, 0);

    // 0: half-0 chain
    gemm_mma<true><<<dim3(HWP/128, 1, NHALF), 256, SMEM_BYTES>>>(
        dWcT, x, df, bc, CC, (size_t)CC*HWP, (size_t)CM*HWP, 0);
    cudaStreamWaitEvent(0, evJoin, 0);
    conv_mma<<<dim3(24, NHALF), 256, CONV_SMEM>>>(b_ad, 0);
    gemm_mma<false><<<dim3(HWP/128, PP/128, NHALF), 256, SMEM_BYTES>>>(
        dWfT, dy, out, bf, CM, (size_t)CM*HWP, (size_t)PP*HWP, 0);

    // s2: half-1 chain (dynw already ordered on s2)
    cudaStreamWaitEvent(s2, evW, 0);
    gemm_mma<true><<<dim3(HWP/128, 1, NHALF), 256, SMEM_BYTES, s2>>>(
        dWcT, x, df, bc, CC, (size_t)CC*HWP, (size_t)CM*HWP, NHALF);
    conv_mma<<<dim3(24, NHALF), 256, CONV_SMEM, s2>>>(b_ad, NHALF);
    gemm_mma<false><<<dim3(HWP/128, PP/128, NHALF), 256, SMEM_BYTES, s2>>>(
        dWfT, dy, out, bf, CM, (size_t)CM*HWP, (size_t)PP*HWP, NHALF);
    cudaEventRecord(evA, s2);

    // join back to stream 0
    cudaStreamWaitEvent(0, evA, 0);
}

// round 16
// speedup vs baseline: 1.4033x; 1.4033x over previous
#include <cuda_runtime.h>
#include <cuda_bf16.h>
#include <cstdint>

// Problem constants
#define NN 32
#define CC 512
#define CM 128
#define HH 48
#define WW 48
#define HWP 2304
#define PP 512
#define KR 9

// ---------------- scratch (device globals; no allocation allowed) ----------
__device__ float g_pool[NN*CC*12];   // [n][c][12]: mean, 9 region-maxes, pad
__device__ float g_gk1[NN*CM];
__device__ float g_sk[NN*CM*KR];
// bf16-triple A-layout buffers (u32 words; 6 words per 4 fp32 k-elements)
__device__ __align__(16) uint32_t g_dynWT[(size_t)NN*KR*CM*192]; // [n][kk][o][192]
__device__ __align__(16) uint32_t g_WcT[CM*768];                 // [o][768]
__device__ __align__(16) uint32_t g_WfT[PP*192];                 // [p][192]
__device__ __align__(16) float g_f[(size_t)NN*CM*HWP];           // [n][o][hw]
__device__ __align__(16) float g_y[(size_t)NN*CM*HWP];           // [n][o][hw]

// ---------------- helpers ----------------------------------------------------
__device__ __forceinline__ uint32_t su32(const void* p){
    uint32_t a; asm("{ .reg .u64 t; cvta.to.shared.u64 t, %1; cvt.u32.u64 %0, t; }"
                    : "=r"(a) : "l"(p)); return a;
}
__device__ __forceinline__ void cpa16(uint32_t d, const void* s){
    asm volatile("cp.async.cg.shared.global [%0], [%1], 16;" :: "r"(d), "l"(s));
}
__device__ __forceinline__ void cpcommit(){ asm volatile("cp.async.commit_group;" ::: "memory"); }
template<int N> __device__ __forceinline__ void cpwait(){
    asm volatile("cp.async.wait_group %0;" :: "n"(N) : "memory");
}
// bf16 m16n8k16 MMA
__device__ __forceinline__ void mma16(float* c, const uint32_t* a, const uint32_t* b){
    asm volatile("mma.sync.aligned.m16n8k16.row.col.f32.bf16.bf16.f32 "
        "{%0,%1,%2,%3}, {%4,%5,%6,%7}, {%8,%9}, {%0,%1,%2,%3};"
        : "+f"(c[0]), "+f"(c[1]), "+f"(c[2]), "+f"(c[3])
        : "r"(a[0]), "r"(a[1]), "r"(a[2]), "r"(a[3]), "r"(b[0]), "r"(b[1]));
}
// ldmatrix x4 (b16, non-transposed)
__device__ __forceinline__ void ldmA(uint32_t* a, uint32_t saddr){
    asm volatile("ldmatrix.sync.aligned.m8n8.x4.shared.b16 {%0,%1,%2,%3}, [%4];"
      : "=r"(a[0]), "=r"(a[1]), "=r"(a[2]), "=r"(a[3]) : "r"(saddr));
}
// 2-term bf16 split: f = hi + lo (+ O(2^-17 f))
__device__ __forceinline__ void bsplit(float f, uint16_t& h, uint16_t& l){
    __nv_bfloat16 bh = __float2bfloat16(f);
    float r = f - __bfloat162float(bh);
    __nv_bfloat16 bl = __float2bfloat16(r);
    h = __bfloat16_as_ushort(bh);
    l = __bfloat16_as_ushort(bl);
}
__device__ __forceinline__ uint32_t pk(uint16_t a, uint16_t b){
    return (uint32_t)a | ((uint32_t)b << 16);
}
// A triple encode: 4 consecutive fp32 k -> 6 u32 words
__device__ __forceinline__ void storeA4(uint32_t* dst, float4 v){
    uint16_t h0,l0,h1,l1,h2,l2,h3,l3;
    bsplit(v.x, h0, l0); bsplit(v.y, h1, l1);
    bsplit(v.z, h2, l2); bsplit(v.w, h3, l3);
    *(uint2*)(dst)     = make_uint2(pk(h0,l0), pk(h0,h1));
    *(uint2*)(dst + 2) = make_uint2(pk(l1,h1), pk(h2,l2));
    *(uint2*)(dst + 4) = make_uint2(pk(h2,h3), pk(l3,h3));
}
// B triple encode: two consecutive fp32 k rows (k even), 4 cols -> 3 swizzled uint4
__device__ __forceinline__ void storeB2x4(uint32_t* bw, int wp, int bn4,
                                          const float* r0, const float* r1){
    uint32_t w0[4], w1[4], w2[4];
#pragma unroll
    for (int j = 0; j < 4; j++) {
        uint16_t H0,L0,H1,L1;
        bsplit(r0[j], H0, L0);
        bsplit(r1[j], H1, L1);
        w0[j] = pk(H0,H0); w1[j] = pk(L0,H1); w2[j] = pk(H1,L1);
    }
    *(uint4*)(bw + (wp  )*128 + (bn4 ^ (((wp  )&3)<<3))) = make_uint4(w0[0],w0[1],w0[2],w0[3]);
    *(uint4*)(bw + (wp+1)*128 + (bn4 ^ (((wp+1)&3)<<3))) = make_uint4(w1[0],w1[1],w1[2],w1[3]);
    *(uint4*)(bw + (wp+2)*128 + (bn4 ^ (((wp+2)&3)<<3))) = make_uint4(w2[0],w2[1],w2[2],w2[3]);
}

// smem geometry (u32 units). A: [128 rows][48 words + pad->52]; B: [48 words][128 cols]
#define AP 52
#define AWBUF (128*AP)          // 6656
#define BWBUF (48*128)          // 6144
#define BUFW  (AWBUF + BWBUF)   // 12800
#define SMEM_BYTES (2*BUFW*4)   // 102400

// conv halo-B: [48 words][6 rows x 50 cols + pad -> 312].
// Fragment bank = (312*lr + col) mod 32 = (24*lr + lq + c) mod 32:
// lr offsets {0,24,16,8} + lq(0..7) -> full 32-lane permutation, conflict-free.
#define CPW 312
#define CBWORDS (48*CPW)                       // 14976 u32
#define CONV_SMEM ((2*AWBUF + CBWORDS)*4)      // 113152 B

// ---------------- kernel 1: mean + 3x3 adaptive max pool (coalesced) -------
__global__ void pool_kernel(const float* __restrict__ x) {
    const int g = threadIdx.x >> 4, l = threadIdx.x & 15;
    const int c = blockIdx.x*16 + g, n = blockIdx.y;
    const float4* xp = (const float4*)(x + (size_t)(n*CC + c)*HWP);

    float s = 0.f;
    float mx[KR];
#pragma unroll
    for (int r = 0; r < KR; r++) {
        const int hb = r/3, wb = r - (r/3)*3;
        float mr = -3.402823466e38f;
#pragma unroll
        for (int j = 0; j < 4; j++) {
            int idx = j*16 + l;
            int row = idx >> 2, w4 = idx & 3;
            float4 v = xp[(hb*16 + row)*12 + wb*4 + w4];
            s += v.x + v.y + v.z + v.w;
            mr = fmaxf(mr, fmaxf(fmaxf(v.x, v.y), fmaxf(v.z, v.w)));
        }
        mx[r] = mr;
    }
#pragma unroll
    for (int o = 8; o > 0; o >>= 1) {
        s += __shfl_down_sync(0xffffffffu, s, o, 16);
#pragma unroll
        for (int r = 0; r < KR; r++)
            mx[r] = fmaxf(mx[r], __shfl_down_sync(0xffffffffu, mx[r], o, 16));
    }
    if (l == 0) {
        float* dst = g_pool + (size_t)(n*CC + c)*12;
        dst[0] = s * (1.0f/(float)HWP);
#pragma unroll
        for (int r = 0; r < KR; r++) dst[1+r] = mx[r];
        dst[10] = 0.f; dst[11] = 0.f;
    }
}

// ---------------- kernel 2: branches (full-chip parallel) -------------------
__global__ void __launch_bounds__(256) branch_kernel(
    const float* __restrict__ Wc, const float* __restrict__ bc) {
    const int og = blockIdx.x, n = blockIdx.y;
    const int lane = threadIdx.x & 31, w = threadIdx.x >> 5;
    const int o0 = og*16 + w*2;
    const int o1 = o0 + 1;

    const float* pb = g_pool + (size_t)n*CC*12;
    const float* wr0 = Wc + (size_t)o0*CC;
    const float* wr1 = Wc + (size_t)o1*CC;

    float a0[10], a1[10];
#pragma unroll
    for (int j = 0; j < 10; j++) { a0[j] = 0.f; a1[j] = 0.f; }

#pragma unroll
    for (int i = 0; i < 16; i++) {
        const int c = lane + i*32;
        const float wv0 = __ldg(&wr0[c]);
        const float wv1 = __ldg(&wr1[c]);
        const float4* pc = (const float4*)(pb + c*12);
        float4 p0 = __ldg(pc), p1 = __ldg(pc+1), p2 = __ldg(pc+2);
        a0[0] += wv0*p0.x; a0[1] += wv0*p0.y; a0[2] += wv0*p0.z; a0[3] += wv0*p0.w;
        a0[4] += wv0*p1.x; a0[5] += wv0*p1.y; a0[6] += wv0*p1.z; a0[7] += wv0*p1.w;
        a0[8] += wv0*p2.x; a0[9] += wv0*p2.y;
        a1[0] += wv1*p0.x; a1[1] += wv1*p0.y; a1[2] += wv1*p0.z; a1[3] += wv1*p0.w;
        a1[4] += wv1*p1.x; a1[5] += wv1*p1.y; a1[6] += wv1*p1.z; a1[7] += wv1*p1.w;
        a1[8] += wv1*p2.x; a1[9] += wv1*p2.y;
    }
#pragma unroll
    for (int off = 16; off > 0; off >>= 1)
#pragma unroll
        for (int j = 0; j < 10; j++) {
            a0[j] += __shfl_down_sync(0xffffffffu, a0[j], off);
            a1[j] += __shfl_down_sync(0xffffffffu, a1[j], off);
        }
    if (lane == 0) {
        const float bv0 = bc[o0], bv1 = bc[o1];
        g_gk1[n*CM + o0] = fmaxf(a0[0] + bv0, 0.f);
        g_gk1[n*CM + o1] = fmaxf(a1[0] + bv1, 0.f);
#pragma unroll
        for (int r = 0; r < KR; r++) {
            g_sk[(size_t)(n*CM + o0)*KR + r] = fmaxf(a0[1+r] + bv0, 0.f);
            g_sk[(size_t)(n*CM + o1)*KR + r] = fmaxf(a1[1+r] + bv1, 0.f);
        }
    }
}

// ---------------- weight triple-encode (one-shot, tiny) ---------------------
__global__ void wtrip_kernel(const float* __restrict__ W, uint32_t* __restrict__ T, int Kd) {
    const int idx = blockIdx.x*256 + threadIdx.x;
    const int gpr = Kd >> 2;
    const int row = idx / gpr, g = idx - row*gpr;
    float4 v = *(const float4*)(W + (size_t)row*Kd + 4*g);
    storeA4(T + (size_t)row*(gpr*6) + 6*g, v);
}

// ---------------- kernel 3: dynamic weights, emitted in trip layout ---------
__global__ void dynw_kernel(const float* __restrict__ Wkk, const float* __restrict__ bkk,
                            const float* __restrict__ Wck, const float* __restrict__ bck) {
    int r = blockIdx.x, n = blockIdx.y;
    int tid = threadIdx.x;
    __shared__ float s_gk[CM], s_sk[CM];
    if (tid < CM) {
        float gk1 = g_gk1[n*CM + tid];
        s_gk[tid] = gk1 * Wkk[r] + bkk[r];
        s_sk[tid] = g_sk[(size_t)(n*CM + tid)*KR + r];
    }
    __syncthreads();
    uint32_t* dst = g_dynWT + (size_t)(n*KR + r)*CM*192;
#pragma unroll
    for (int i = 0; i < 16; i++) {
        const int idx = tid + i*256;
        const int o = idx >> 5, gc = idx & 31;
        const int c4 = gc*4;
        const float wa = Wck[o*2], wb = Wck[o*2+1], bo = bck[o];
        float4 v;
        v.x = fmaxf(wa*s_gk[c4]   + wb*s_sk[c4]   + bo, 0.f);
        v.y = fmaxf(wa*s_gk[c4+1] + wb*s_sk[c4+1] + bo, 0.f);
        v.z = fmaxf(wa*s_gk[c4+2] + wb*s_sk[c4+2] + bo, 0.f);
        v.w = fmaxf(wa*s_gk[c4+3] + wb*s_sk[c4+3] + bo, 0.f);
        storeA4(dst + (size_t)o*192 + gc*6, v);
    }
}

// ---------------- shared bf16 mma compute (ldmatrix A + LDS B) --------------
__device__ __forceinline__ void mma_compute(
    uint32_t aAddr, const uint32_t* pb, float acc[2][8][4],
    int wn, int lane)
{
    const int lq = lane >> 2, lr = lane & 3;
#pragma unroll
    for (int s = 0; s < 6; s++) {
        uint32_t a[2][4];
        ldmA(a[0], aAddr + s*32);
        ldmA(a[1], aAddr + 16*AP*4 + s*32);
        const int w0 = s*8 + lr;
        const int xr = (w0 & 3) << 3;
        const int nb = wn*64 + lq;
#pragma unroll
        for (int nt = 0; nt < 8; nt++) {
            const int col = (nb + nt*8) ^ xr;
            uint32_t b[2];
            b[0] = pb[w0*128 + col];
            b[1] = pb[(w0+4)*128 + col];
            mma16(acc[0][nt], a[0], b);
            mma16(acc[1][nt], a[1], b);
        }
    }
}

// ---------------- bf16x3 mma GEMM: C[n] = act(At @ B[n] + bias) --------------
template<bool RELU>
__global__ void __launch_bounds__(256, 2) gemm_mma(
    const uint32_t* __restrict__ At, const float* __restrict__ B,
    float* __restrict__ C, const float* __restrict__ bias,
    int Kd, size_t BstrN, size_t CstrN)
{
    extern __shared__ uint32_t sm[];
    const uint32_t sBase = su32(sm);

    const int tid = threadIdx.x, lane = tid & 31, wid = tid >> 5;
    const int wm = wid & 3, wn = wid >> 2;
    const int n0 = blockIdx.x * 128;
    const int m0 = blockIdx.y * 128;
    const int nb = blockIdx.z;
    const int W3 = (Kd >> 2) * 6;
    const float* Bp = B + (size_t)nb*BstrN + n0;
    float*       Cp = C + (size_t)nb*CstrN;

    const int kb2 = (tid >> 5) * 2;
    const int bn4 = (tid & 31) * 4;

    const uint32_t aAddr0 = sBase + (uint32_t)((wm*32 + (lane & 15))*AP + (lane >> 4)*4)*4;

    float acc[2][8][4];
#pragma unroll
    for (int i = 0; i < 2; i++)
#pragma unroll
        for (int j = 0; j < 8; j++)
#pragma unroll
            for (int t = 0; t < 4; t++) acc[i][j][t] = 0.f;

    float4 rB[2][2];

    auto cpA = [&](int it){
        const int buf = it & 1;
#pragma unroll
        for (int j = 0; j < 6; j++) {
            const int ch = tid + j*256;
            const int row = ch / 12, w16 = ch - row*12;
            cpa16(sBase + (uint32_t)(buf*BUFW + row*AP + w16*4)*4,
                  At + (size_t)(m0 + row)*W3 + it*48 + w16*4);
        }
        cpcommit();
    };
    auto ldgB = [&](int it){
        const int k0 = it * 32;
#pragma unroll
        for (int q = 0; q < 2; q++) {
            const int k = k0 + kb2 + q*16;
            rB[q][0] = *(const float4*)(Bp + (size_t)k*HWP + bn4);
            rB[q][1] = *(const float4*)(Bp + (size_t)(k+1)*HWP + bn4);
        }
    };
    auto stsB = [&](int buf){
        uint32_t* bw = sm + buf*BUFW + AWBUF;
#pragma unroll
        for (int q = 0; q < 2; q++)
            storeB2x4(bw, ((tid>>5) + q*8)*3, bn4, (const float*)&rB[q][0], (const float*)&rB[q][1]);
    };

    const int nIter = Kd / 32;
    cpA(0); ldgB(0); stsB(0); cpwait<0>(); __syncthreads();
    for (int it = 0; it < nIter; ++it) {
        const int cur = it & 1;
        if (it + 1 < nIter) { cpA(it + 1); ldgB(it + 1); }
        mma_compute(aAddr0 + cur*BUFW*4, sm + cur*BUFW + AWBUF, acc, wn, lane);
        if (it + 1 < nIter) { stsB(cur ^ 1); cpwait<0>(); __syncthreads(); }
    }

    const int lq = lane >> 2, lr = lane & 3;
#pragma unroll
    for (int mt = 0; mt < 2; mt++) {
        const int r0 = m0 + wm*32 + mt*16 + lq;
        const float bv0 = __ldg(&bias[r0]);
        const float bv1 = __ldg(&bias[r0 + 8]);
#pragma unroll
        for (int nt = 0; nt < 8; nt++) {
            const int cb = n0 + wn*64 + nt*8 + 2*lr;
            float2 v0 = make_float2(acc[mt][nt][0] + bv0, acc[mt][nt][1] + bv0);
            float2 v1 = make_float2(acc[mt][nt][2] + bv1, acc[mt][nt][3] + bv1);
            if (RELU) {
                v0.x = fmaxf(v0.x, 0.f); v0.y = fmaxf(v0.y, 0.f);
                v1.x = fmaxf(v1.x, 0.f); v1.y = fmaxf(v1.y, 0.f);
            }
            *(float2*)(Cp + (size_t)r0*HWP + cb)       = v0;
            *(float2*)(Cp + (size_t)(r0 + 8)*HWP + cb) = v1;
        }
    }
}

// ---------------- conv: halo-tiled implicit GEMM, 192-hw tile (bf16x3) -------
// Block (512 threads): output 128 o x 192 hw (4 image rows h0..h0+3).
// B smem: trip f tile [48 words][6 rows x 50 w] loaded once per 32-c chunk;
// output row h0+wn (wn=0..3) reads tile rows wn..wn+2 via tapoff = kh*50+kw.
__global__ void __launch_bounds__(512, 1) conv_mma(const float* __restrict__ b_ad)
{
    extern __shared__ uint32_t sm[];
    const uint32_t sBase = su32(sm);
    uint32_t* bw = sm + 2*AWBUF;

    const int tid = threadIdx.x, lane = tid & 31, wid = tid >> 5;
    const int wm = wid & 3, wn = wid >> 2;   // wm: 32-o rows; wn: output row 0..3
    const int bx = blockIdx.x;               // 12 tiles of 4 rows
    const int h0 = bx*4;
    const int hw0 = bx*192;
    const int nb  = blockIdx.y;
    const float* fb = g_f + (size_t)nb*CM*HWP;
    const uint32_t* dwt = g_dynWT + (size_t)nb*KR*CM*192;

    const uint32_t aAddr0 = sBase + (uint32_t)((wm*32 + (lane & 15))*AP + (lane >> 4)*4)*4;

    // zero the 12 pad columns (w=-1, w=48 per input row r=0..5) for all 48 k-words
    for (int i = tid; i < 48*12; i += 512) {
        const int row = i / 12, e = i % 12;
        const int r = e >> 1, side = e & 1;
        bw[row*CPW + r*50 + (side ? 49 : 0)] = 0;
    }

    float acc[2][6][4];
#pragma unroll
    for (int i = 0; i < 2; i++)
#pragma unroll
        for (int j = 0; j < 6; j++)
#pragma unroll
            for (int t = 0; t < 4; t++) acc[i][j][t] = 0.f;

    auto cpA = [&](int it){                 // it = chunk*9 + kk
        const int buf = it & 1;
        const int kk = it % 9, c48 = (it/9)*48;
        const uint32_t* src = dwt + (size_t)kk*CM*192;
#pragma unroll
        for (int j = 0; j < 3; j++) {
            const int ch = tid + j*512;      // 0..1535 16B chunks
            const int row = ch / 12, w16 = ch - row*12;
            cpa16(sBase + (uint32_t)(buf*AWBUF + row*AP + w16*4)*4,
                  src + (size_t)row*192 + c48 + w16*4);
        }
        cpcommit();
    };

    auto loadB = [&](int chunk){
        const int c0 = chunk*32;
#pragma unroll
        for (int j = 0; j < 9; j++) {
            const int slot = tid + j*512;    // 0..4607 = 16 pairs x 6 rows x 48 w
            const int p = slot / 288, pos = slot - p*288;
            const int r = pos / 48, w = pos - r*48;
            const int hin = h0 - 1 + r;
            const bool ok = (hin >= 0) && (hin < HH);
            float v0 = 0.f, v1 = 0.f;
            if (ok) {
                const float* fp = fb + (size_t)(c0 + 2*p)*HWP + hin*WW + w;
                v0 = __ldg(fp);
                v1 = __ldg(fp + HWP);
            }
            uint16_t H0,L0,H1,L1;
            bsplit(v0, H0, L0); bsplit(v1, H1, L1);
            uint32_t* q = bw + (3*p)*CPW + r*50 + 1 + w;
            q[0]     = pk(H0,H0);
            q[CPW]   = pk(L0,H1);
            q[2*CPW] = pk(H1,L1);
        }
    };

    const int lq = lane >> 2, lr = lane & 3;
    const int colb = (wn + 1)*50 + 1 + lq;   // fragment col base (tap 0 center)

    auto mmaStep = [&](int buf, int tapoff){
        const uint32_t aAddr = aAddr0 + (uint32_t)(buf*AWBUF)*4;
#pragma unroll
        for (int s = 0; s < 6; s++) {
            uint32_t a[2][4];
            ldmA(a[0], aAddr + s*32);
            ldmA(a[1], aAddr + 16*AP*4 + s*32);
            const uint32_t* pb0 = bw + (s*8 + lr)*CPW + tapoff;
#pragma unroll
            for (int nt = 0; nt < 6; nt++) {
                const int col = colb + nt*8;
                uint32_t b[2];
                b[0] = pb0[col];
                b[1] = pb0[4*CPW + col];
                mma16(acc[0][nt], a[0], b);
                mma16(acc[1][nt], a[1], b);
            }
        }
    };

    cpA(0); cpwait<0>();
    for (int chunk = 0; chunk < 4; chunk++) {
        __syncthreads();                 // prior readers done / zeros+A visible
        loadB(chunk);
        __syncthreads();
#pragma unroll
        for (int kk = 0; kk < KR; kk++) {
            const int it = chunk*9 + kk;
            if (it + 1 < 36) cpA(it + 1);
            const int kh = kk/3 - 1, kw = kk - (kk/3)*3 - 1;
            mmaStep(it & 1, kh*50 + kw);
            if (it + 1 < 36) { cpwait<0>(); __syncthreads(); }
        }
    }

    // epilogue: y[o][hw0 + wn*48 + nt*8 + 2lr + {0,1}]
    float* yb = g_y + (size_t)nb*CM*HWP;
#pragma unroll
    for (int mt = 0; mt < 2; mt++) {
        const int o0 = wm*32 + mt*16 + lq;
        const float bv0 = __ldg(&b_ad[o0]);
        const float bv1 = __ldg(&b_ad[o0 + 8]);
#pragma unroll
        for (int nt = 0; nt < 6; nt++) {
            const int cb = hw0 + wn*48 + nt*8 + 2*lr;
            float2 v0 = make_float2(acc[mt][nt][0] + bv0, acc[mt][nt][1] + bv0);
            float2 v1 = make_float2(acc[mt][nt][2] + bv1, acc[mt][nt][3] + bv1);
            *(float2*)(yb + (size_t)o0*HWP + cb)       = v0;
            *(float2*)(yb + (size_t)(o0 + 8)*HWP + cb) = v1;
        }
    }
}

// ---------------- launch -----------------------------------------------------
// Round-12-proven schedule: side chain forked on one stream, mma chain serial.
extern "C" void kernel_launch(void* const* d_in, const int* in_sizes, int n_in,
                              void* d_out, int out_size) {
    const float* x    = (const float*)d_in[0];
    const float* Wc   = (const float*)d_in[1];
    const float* bc   = (const float*)d_in[2];
    const float* Wkk  = (const float*)d_in[3];
    const float* bkk  = (const float*)d_in[4];
    const float* Wck  = (const float*)d_in[5];
    const float* bck  = (const float*)d_in[6];
    const float* b_ad = (const float*)d_in[7];
    const float* Wf   = (const float*)d_in[8];
    const float* bf   = (const float*)d_in[9];
    float* out = (float*)d_out;

    float* df; float* dy;
    uint32_t* dWcT; uint32_t* dWfT;
    cudaGetSymbolAddress((void**)&df,   g_f);
    cudaGetSymbolAddress((void**)&dy,   g_y);
    cudaGetSymbolAddress((void**)&dWcT, g_WcT);
    cudaGetSymbolAddress((void**)&dWfT, g_WfT);

    cudaFuncSetAttribute(gemm_mma<true>,  cudaFuncAttributeMaxDynamicSharedMemorySize, SMEM_BYTES);
    cudaFuncSetAttribute(gemm_mma<false>, cudaFuncAttributeMaxDynamicSharedMemorySize, SMEM_BYTES);
    cudaFuncSetAttribute(conv_mma,        cudaFuncAttributeMaxDynamicSharedMemorySize, CONV_SMEM);

    cudaStream_t s2;
    cudaStreamCreateWithFlags(&s2, cudaStreamNonBlocking);
    cudaEvent_t evFork, evJoin;
    cudaEventCreateWithFlags(&evFork, cudaEventDisableTiming);
    cudaEventCreateWithFlags(&evJoin, cudaEventDisableTiming);

    // fork: side chain pool -> branch -> dynw on s2
    cudaEventRecord(evFork, 0);
    cudaStreamWaitEvent(s2, evFork, 0);
    pool_kernel<<<dim3(CC/16, NN), 256, 0, s2>>>(x);
    branch_kernel<<<dim3(8, NN), 256, 0, s2>>>(Wc, bc);
    dynw_kernel<<<dim3(KR, NN), 256, 0, s2>>>(Wkk, bkk, Wck, bck);
    cudaEventRecord(evJoin, s2);

    // main stream: weight encodes + gemm1 (independent of the side chain)
    wtrip_kernel<<<CM*(CC/4)/256, 256>>>(Wc, dWcT, CC);
    wtrip_kernel<<<PP*(CM/4)/256, 256>>>(Wf, dWfT, CM);
    gemm_mma<true><<<dim3(HWP/128, 1, NN), 256, SMEM_BYTES>>>(
        dWcT, x, df, bc, CC, (size_t)CC*HWP, (size_t)CM*HWP);

    // join: conv needs gemm1 (f) + dynw (dynWT)
    cudaStreamWaitEvent(0, evJoin, 0);
    conv_mma<<<dim3(12, NN), 512, CONV_SMEM>>>(b_ad);

    // out = Wf @ y + bf
    gemm_mma<false><<<dim3(HWP/128, PP/128, NN), 256, SMEM_BYTES>>>(
        dWfT, dy, out, bf, CM, (size_t)CM*HWP, (size_t)PP*HWP);
}